// round 15
// baseline (speedup 1.0000x reference)
#include <cuda_runtime.h>

// DCRNN encoder (2-layer DCGRU), fp32. B=16,T=32,N=128,D=H=128,K=2 (M=3).
// d_out = [finals (L*B*N*H = 524288 floats) | layer-1 out seq (T*B*N*H = 8388608)]

#define Tn 32
#define Bn 16

typedef unsigned long long ull;

// ---------------- static device scratch (no allocs allowed) ----------------
__device__ float g_Wx[2][384 * 384];    // x-part weights [A;B;C] -> [gates(256)|cand(128)]
__device__ float g_Whg[2][384 * 256];   // h-part gate weights [A;B;C]
__device__ float g_Whc[2][384 * 128];   // h-part cand weights [A;B;C]
__device__ float g_S2[Tn * 128 * 128];      // S_t @ S_t
__device__ float g_XS[Tn * Bn * 128 * 128]; // S   @ x per (t,b)
__device__ float g_X2S[Tn * Bn * 128 * 128];// S^2 @ x
__device__ float g_PRE[Tn * Bn * 128 * 384];// x-contribution (+bias): 0..255 gates, 256..383 cand
__device__ float g_H[Bn * 128 * 128];   // current hidden
__device__ float g_RH[Bn * 128 * 128];  // r * h
__device__ float g_U[Bn * 128 * 128];   // u gate
__device__ float g_OUT0[Tn * Bn * 128 * 128]; // layer-0 output sequence

// ---------------- f32x2 helpers --------------------------------------------
__device__ __forceinline__ ull pk2(float a, float b) {
    ull r;
    asm("mov.b64 %0,{%1,%2};" : "=l"(r) : "r"(__float_as_uint(a)), "r"(__float_as_uint(b)));
    return r;
}
__device__ __forceinline__ ull dup2(float a) { return pk2(a, a); }
__device__ __forceinline__ void upk2(ull v, float& a, float& b) {
    unsigned int x, y;
    asm("mov.b64 {%0,%1},%2;" : "=r"(x), "=r"(y) : "l"(v));
    a = __uint_as_float(x); b = __uint_as_float(y);
}
__device__ __forceinline__ void fma2(ull& c, ull a, ull b) {
    asm("fma.rn.f32x2 %0,%1,%2,%0;" : "+l"(c) : "l"(a), "l"(b));
}

__device__ __forceinline__ void cpy4(float* dst, const float* __restrict__ src, int n4, int tid) {
    float4* d = (float4*)dst;
    const float4* s = (const float4*)src;
    for (int i = tid; i < n4; i += 256) d[i] = s[i];
}

// ---------------- weight prep: fold Chebyshev into [A;B;C] -----------------
__global__ void k_prep_w(const float* __restrict__ Wg0, const float* __restrict__ Wc0,
                         const float* __restrict__ Wg1, const float* __restrict__ Wc1) {
    int idx = blockIdx.x * 256 + threadIdx.x;
    const int PER = 147456 + 98304 + 49152;  // 294912 per layer
    if (idx >= 2 * PER) return;
    int layer = idx / PER, r = idx % PER;
    const float* Wg = layer ? Wg1 : Wg0;
    const float* Wc = layer ? Wc1 : Wc0;
    if (r < 147456) {                       // g_Wx [384][384] : x features (dcat = k)
        int k2 = r / 384, o = r % 384, part = k2 >> 7, k = k2 & 127;
        const float* W; int oc, oo;
        if (o < 256) { W = Wg; oc = 256; oo = o; } else { W = Wc; oc = 128; oo = o - 256; }
        int base = k * 3;
        float v = (part == 0) ? W[(base + 0) * oc + oo] - W[(base + 2) * oc + oo]
                : (part == 1) ? W[(base + 1) * oc + oo]
                              : 2.f * W[(base + 2) * oc + oo];
        g_Wx[layer][k2 * 384 + o] = v;
    } else if (r < 245760) {                // g_Whg [384][256] : h features (dcat = 128+k)
        int rr = r - 147456, k2 = rr / 256, o = rr % 256, part = k2 >> 7, k = k2 & 127;
        int base = (128 + k) * 3;
        float v = (part == 0) ? Wg[(base + 0) * 256 + o] - Wg[(base + 2) * 256 + o]
                : (part == 1) ? Wg[(base + 1) * 256 + o]
                              : 2.f * Wg[(base + 2) * 256 + o];
        g_Whg[layer][k2 * 256 + o] = v;
    } else {                                // g_Whc [384][128]
        int rr = r - 245760, k2 = rr / 128, o = rr % 128, part = k2 >> 7, k = k2 & 127;
        int base = (128 + k) * 3;
        float v = (part == 0) ? Wc[(base + 0) * 128 + o] - Wc[(base + 2) * 128 + o]
                : (part == 1) ? Wc[(base + 1) * 128 + o]
                              : 2.f * Wc[(base + 2) * 128 + o];
        g_Whc[layer][k2 * 128 + o] = v;
    }
}

// ---------------- S2[t] = S_t @ S_t  (grid: 32 x 4, tile 32x128) -----------
__global__ void __launch_bounds__(256)
k_s2(const float* __restrict__ sup) {
    extern __shared__ float sm[];
    float* sX = sm;            // 128x128
    float* sA = sm + 16384;    // 32x128
    int tid = threadIdx.x, tx = tid & 31, ty = tid >> 5;
    int t = blockIdx.x, r0 = blockIdx.y * 32;
    const float* S = sup + t * 16384;
    cpy4(sX, S, 4096, tid);
    cpy4(sA, S + r0 * 128, 1024, tid);
    __syncthreads();
    ull acc[4][2] = {};
#pragma unroll 4
    for (int k = 0; k < 128; k++) {
        ulonglong2 bv = *(const ulonglong2*)(sX + k * 128 + tx * 4);
#pragma unroll
        for (int i = 0; i < 4; i++) {
            ull av = dup2(sA[(ty * 4 + i) * 128 + k]);
            fma2(acc[i][0], av, bv.x);
            fma2(acc[i][1], av, bv.y);
        }
    }
#pragma unroll
    for (int i = 0; i < 4; i++) {
        float4 v;
        upk2(acc[i][0], v.x, v.y);
        upk2(acc[i][1], v.z, v.w);
        *(float4*)(g_S2 + t * 16384 + (r0 + ty * 4 + i) * 128 + tx * 4) = v;
    }
}

// ------- XS = S@x, X2S = S^2@x for all (t,b) (grid: 512 x 4) ---------------
__global__ void __launch_bounds__(256)
k_pre_graph(const float* __restrict__ Xin, int mode, const float* __restrict__ sup) {
    extern __shared__ float sm[];
    float* sX  = sm;           // 16384
    float* sA  = sm + 16384;   // 4096
    float* sA2 = sm + 20480;   // 4096
    int tid = threadIdx.x, tx = tid & 31, ty = tid >> 5;
    int tb = blockIdx.x, t = tb >> 4, b = tb & 15, r0 = blockIdx.y * 32;
    const float* X = (mode == 0) ? Xin + (size_t)(b * Tn + t) * 16384
                                 : g_OUT0 + (size_t)tb * 16384;
    cpy4(sX, X, 4096, tid);
    cpy4(sA,  sup  + t * 16384 + r0 * 128, 1024, tid);
    cpy4(sA2, g_S2 + t * 16384 + r0 * 128, 1024, tid);
    __syncthreads();
    ull a1[4][2] = {}, a2[4][2] = {};
#pragma unroll 2
    for (int k = 0; k < 128; k++) {
        ulonglong2 bv = *(const ulonglong2*)(sX + k * 128 + tx * 4);
#pragma unroll
        for (int i = 0; i < 4; i++) {
            ull av = dup2(sA[(ty * 4 + i) * 128 + k]);
            fma2(a1[i][0], av, bv.x);
            fma2(a1[i][1], av, bv.y);
            ull aw = dup2(sA2[(ty * 4 + i) * 128 + k]);
            fma2(a2[i][0], aw, bv.x);
            fma2(a2[i][1], aw, bv.y);
        }
    }
#pragma unroll
    for (int i = 0; i < 4; i++) {
        float4 v;
        upk2(a1[i][0], v.x, v.y); upk2(a1[i][1], v.z, v.w);
        *(float4*)(g_XS + (size_t)tb * 16384 + (r0 + ty * 4 + i) * 128 + tx * 4) = v;
        upk2(a2[i][0], v.x, v.y); upk2(a2[i][1], v.z, v.w);
        *(float4*)(g_X2S + (size_t)tb * 16384 + (r0 + ty * 4 + i) * 128 + tx * 4) = v;
    }
}

// ------- PRE = [x|Sx|S2x]@Wx + bias (grid: 512 x 4 x 3) --------------------
__global__ void __launch_bounds__(256)
k_pre_dense(const float* __restrict__ Xin, int mode, int layer,
            const float* __restrict__ bg, const float* __restrict__ bc) {
    extern __shared__ float sm[];
    float* sA = sm;            // 4096 (32x128)
    float* sW = sm + 4096;     // 16384 (128x128)
    int tid = threadIdx.x, tx = tid & 31, ty = tid >> 5;
    int tb = blockIdx.x, t = tb >> 4, b = tb & 15;
    int r0 = blockIdx.y * 32, c0 = blockIdx.z * 128;
    const float* W = g_Wx[layer];
    ull acc[4][2] = {};
    for (int ch = 0; ch < 3; ch++) {
        const float* As;
        if (ch == 0)
            As = (mode == 0) ? Xin + (size_t)(b * Tn + t) * 16384
                             : g_OUT0 + (size_t)tb * 16384;
        else if (ch == 1) As = g_XS + (size_t)tb * 16384;
        else              As = g_X2S + (size_t)tb * 16384;
        __syncthreads();
        cpy4(sA, As + r0 * 128, 1024, tid);
        for (int i = tid; i < 4096; i += 256) {
            int kk = i >> 5, cc = (i & 31) * 4;
            *(float4*)(sW + kk * 128 + cc) =
                *(const float4*)(W + (size_t)(ch * 128 + kk) * 384 + c0 + cc);
        }
        __syncthreads();
#pragma unroll 4
        for (int k = 0; k < 128; k++) {
            ulonglong2 bv = *(const ulonglong2*)(sW + k * 128 + tx * 4);
#pragma unroll
            for (int i = 0; i < 4; i++) {
                ull av = dup2(sA[(ty * 4 + i) * 128 + k]);
                fma2(acc[i][0], av, bv.x);
                fma2(acc[i][1], av, bv.y);
            }
        }
    }
    int oc = c0 + tx * 4;
    float4 bias;
    if (oc < 256) bias = *(const float4*)(bg + oc);
    else          bias = *(const float4*)(bc + oc - 256);
#pragma unroll
    for (int i = 0; i < 4; i++) {
        float4 v;
        upk2(acc[i][0], v.x, v.y); upk2(acc[i][1], v.z, v.w);
        v.x += bias.x; v.y += bias.y; v.z += bias.z; v.w += bias.w;
        *(float4*)(g_PRE + ((size_t)tb * 128 + r0 + ty * 4 + i) * 384 + oc) = v;
    }
}

// ------- per-step kernel 1: graph-conv(h) + gate GEMM + sigmoid + r*h ------
// grid (16 batches, 4 row-tiles, 2 col-tiles[r|u]), 192KB smem
__global__ void __launch_bounds__(256)
k_gates(int t, int layer, const float* __restrict__ sup) {
    extern __shared__ float sm[];
    float* sHb  = sm;           // 16384 : full h_b
    float* sS   = sm + 16384;   // 4096
    float* sS2  = sm + 20480;   // 4096
    float* sSh  = sm + 24576;   // 4096
    float* sS2h = sm + 28672;   // 4096
    float* sW   = sm + 32768;   // 16384
    int tid = threadIdx.x, tx = tid & 31, ty = tid >> 5;
    int b = blockIdx.x, r0 = blockIdx.y * 32, ct = blockIdx.z, c0 = ct * 128;
    cpy4(sHb, g_H + b * 16384, 4096, tid);
    cpy4(sS,  sup  + t * 16384 + r0 * 128, 1024, tid);
    cpy4(sS2, g_S2 + t * 16384 + r0 * 128, 1024, tid);
    __syncthreads();
    // phase 1: Sh, S2h row tiles
    {
        ull a1[4][2] = {}, a2[4][2] = {};
#pragma unroll 2
        for (int k = 0; k < 128; k++) {
            ulonglong2 bv = *(const ulonglong2*)(sHb + k * 128 + tx * 4);
#pragma unroll
            for (int i = 0; i < 4; i++) {
                ull av = dup2(sS[(ty * 4 + i) * 128 + k]);
                fma2(a1[i][0], av, bv.x); fma2(a1[i][1], av, bv.y);
                ull aw = dup2(sS2[(ty * 4 + i) * 128 + k]);
                fma2(a2[i][0], aw, bv.x); fma2(a2[i][1], aw, bv.y);
            }
        }
#pragma unroll
        for (int i = 0; i < 4; i++) {
            float4 v;
            upk2(a1[i][0], v.x, v.y); upk2(a1[i][1], v.z, v.w);
            *(float4*)(sSh + (ty * 4 + i) * 128 + tx * 4) = v;
            upk2(a2[i][0], v.x, v.y); upk2(a2[i][1], v.z, v.w);
            *(float4*)(sS2h + (ty * 4 + i) * 128 + tx * 4) = v;
        }
    }
    // phase 2: [h|Sh|S2h] @ Whg[:, c0:c0+128]
    const float* W = g_Whg[layer];
    ull acc[4][2] = {};
    for (int ch = 0; ch < 3; ch++) {
        __syncthreads();
        for (int i = tid; i < 4096; i += 256) {
            int kk = i >> 5, cc = (i & 31) * 4;
            *(float4*)(sW + kk * 128 + cc) =
                *(const float4*)(W + (size_t)(ch * 128 + kk) * 256 + c0 + cc);
        }
        __syncthreads();
        const float* A = (ch == 0) ? sHb + r0 * 128 : (ch == 1) ? sSh : sS2h;
#pragma unroll 4
        for (int k = 0; k < 128; k++) {
            ulonglong2 bv = *(const ulonglong2*)(sW + k * 128 + tx * 4);
#pragma unroll
            for (int i = 0; i < 4; i++) {
                ull av = dup2(A[(ty * 4 + i) * 128 + k]);
                fma2(acc[i][0], av, bv.x);
                fma2(acc[i][1], av, bv.y);
            }
        }
    }
    int tb = t * Bn + b;
#pragma unroll
    for (int i = 0; i < 4; i++) {
        int row = r0 + ty * 4 + i;
        float4 v;
        upk2(acc[i][0], v.x, v.y); upk2(acc[i][1], v.z, v.w);
        float4 p = *(const float4*)(g_PRE + ((size_t)tb * 128 + row) * 384 + c0 + tx * 4);
        v.x = 1.f / (1.f + expf(-(v.x + p.x)));
        v.y = 1.f / (1.f + expf(-(v.y + p.y)));
        v.z = 1.f / (1.f + expf(-(v.z + p.z)));
        v.w = 1.f / (1.f + expf(-(v.w + p.w)));
        int off = b * 16384 + row * 128 + tx * 4;
        if (ct == 0) {  // r gate -> rh
            float4 h = *(const float4*)(sHb + row * 128 + tx * 4);
            v.x *= h.x; v.y *= h.y; v.z *= h.z; v.w *= h.w;
            *(float4*)(g_RH + off) = v;
        } else {        // u gate
            *(float4*)(g_U + off) = v;
        }
    }
}

// ------- per-step kernel 2: graph-conv(rh) + cand GEMM + tanh + GRU update -
// grid (16 batches, 4 row-tiles), 192KB smem
__global__ void __launch_bounds__(256)
k_cand(int t, int layer, const float* __restrict__ sup, float* __restrict__ dout1) {
    extern __shared__ float sm[];
    float* sRb  = sm;           // 16384 : full rh_b
    float* sS   = sm + 16384;
    float* sS2  = sm + 20480;
    float* sSh  = sm + 24576;
    float* sS2h = sm + 28672;
    float* sW   = sm + 32768;
    int tid = threadIdx.x, tx = tid & 31, ty = tid >> 5;
    int b = blockIdx.x, r0 = blockIdx.y * 32;
    cpy4(sRb, g_RH + b * 16384, 4096, tid);
    cpy4(sS,  sup  + t * 16384 + r0 * 128, 1024, tid);
    cpy4(sS2, g_S2 + t * 16384 + r0 * 128, 1024, tid);
    __syncthreads();
    {
        ull a1[4][2] = {}, a2[4][2] = {};
#pragma unroll 2
        for (int k = 0; k < 128; k++) {
            ulonglong2 bv = *(const ulonglong2*)(sRb + k * 128 + tx * 4);
#pragma unroll
            for (int i = 0; i < 4; i++) {
                ull av = dup2(sS[(ty * 4 + i) * 128 + k]);
                fma2(a1[i][0], av, bv.x); fma2(a1[i][1], av, bv.y);
                ull aw = dup2(sS2[(ty * 4 + i) * 128 + k]);
                fma2(a2[i][0], aw, bv.x); fma2(a2[i][1], aw, bv.y);
            }
        }
#pragma unroll
        for (int i = 0; i < 4; i++) {
            float4 v;
            upk2(a1[i][0], v.x, v.y); upk2(a1[i][1], v.z, v.w);
            *(float4*)(sSh + (ty * 4 + i) * 128 + tx * 4) = v;
            upk2(a2[i][0], v.x, v.y); upk2(a2[i][1], v.z, v.w);
            *(float4*)(sS2h + (ty * 4 + i) * 128 + tx * 4) = v;
        }
    }
    const float* W = g_Whc[layer];
    ull acc[4][2] = {};
    for (int ch = 0; ch < 3; ch++) {
        __syncthreads();
        for (int i = tid; i < 4096; i += 256) {
            int kk = i >> 5, cc = (i & 31) * 4;
            *(float4*)(sW + kk * 128 + cc) =
                *(const float4*)(W + (size_t)(ch * 128 + kk) * 128 + cc);
        }
        __syncthreads();
        const float* A = (ch == 0) ? sRb + r0 * 128 : (ch == 1) ? sSh : sS2h;
#pragma unroll 4
        for (int k = 0; k < 128; k++) {
            ulonglong2 bv = *(const ulonglong2*)(sW + k * 128 + tx * 4);
#pragma unroll
            for (int i = 0; i < 4; i++) {
                ull av = dup2(A[(ty * 4 + i) * 128 + k]);
                fma2(acc[i][0], av, bv.x);
                fma2(acc[i][1], av, bv.y);
            }
        }
    }
    int tb = t * Bn + b;
    float* outp = layer ? dout1 : g_OUT0;
#pragma unroll
    for (int i = 0; i < 4; i++) {
        int row = r0 + ty * 4 + i;
        float4 v;
        upk2(acc[i][0], v.x, v.y); upk2(acc[i][1], v.z, v.w);
        float4 p = *(const float4*)(g_PRE + ((size_t)tb * 128 + row) * 384 + 256 + tx * 4);
        v.x = tanhf(v.x + p.x);
        v.y = tanhf(v.y + p.y);
        v.z = tanhf(v.z + p.z);
        v.w = tanhf(v.w + p.w);
        int off = b * 16384 + row * 128 + tx * 4;
        float4 u = *(const float4*)(g_U + off);
        float4 h = *(const float4*)(g_H + off);
        float4 hn;
        hn.x = u.x * h.x + (1.f - u.x) * v.x;
        hn.y = u.y * h.y + (1.f - u.y) * v.y;
        hn.z = u.z * h.z + (1.f - u.z) * v.z;
        hn.w = u.w * h.w + (1.f - u.w) * v.w;
        *(float4*)(g_H + off) = hn;
        *(float4*)(outp + (size_t)tb * 16384 + row * 128 + tx * 4) = hn;
    }
}

// ---------------------------------------------------------------------------
extern "C" void kernel_launch(void* const* d_in, const int* in_sizes, int n_in,
                              void* d_out, int out_size) {
    const float* inputs = (const float*)d_in[0];
    const float* ihs    = (const float*)d_in[1];
    const float* sup    = (const float*)d_in[2];
    const float* Wg0 = (const float*)d_in[3];
    const float* bg0 = (const float*)d_in[4];
    const float* Wc0 = (const float*)d_in[5];
    const float* bc0 = (const float*)d_in[6];
    const float* Wg1 = (const float*)d_in[7];
    const float* bg1 = (const float*)d_in[8];
    const float* Wc1 = (const float*)d_in[9];
    const float* bc1 = (const float*)d_in[10];
    float* out = (float*)d_out;

    cudaFuncSetAttribute(k_s2,        cudaFuncAttributeMaxDynamicSharedMemorySize, 81920);
    cudaFuncSetAttribute(k_pre_graph, cudaFuncAttributeMaxDynamicSharedMemorySize, 98304);
    cudaFuncSetAttribute(k_pre_dense, cudaFuncAttributeMaxDynamicSharedMemorySize, 81920);
    cudaFuncSetAttribute(k_gates,     cudaFuncAttributeMaxDynamicSharedMemorySize, 196608);
    cudaFuncSetAttribute(k_cand,      cudaFuncAttributeMaxDynamicSharedMemorySize, 196608);

    float* pH = nullptr;
    cudaGetSymbolAddress((void**)&pH, g_H);

    k_prep_w<<<2304, 256>>>(Wg0, Wc0, Wg1, Wc1);
    k_s2<<<dim3(32, 4), 256, 81920>>>(sup);

    for (int layer = 0; layer < 2; layer++) {
        cudaMemcpyAsync(pH, ihs + (size_t)layer * 262144, 262144 * sizeof(float),
                        cudaMemcpyDeviceToDevice, 0);
        k_pre_graph<<<dim3(512, 4), 256, 98304>>>(inputs, layer, sup);
        k_pre_dense<<<dim3(512, 4, 3), 256, 81920>>>(
            inputs, layer, layer, layer ? bg1 : bg0, layer ? bc1 : bc0);
        for (int t = 0; t < Tn; t++) {
            k_gates<<<dim3(16, 4, 2), 256, 196608>>>(t, layer, sup);
            k_cand<<<dim3(16, 4), 256, 196608>>>(t, layer, sup, out + 524288);
        }
        // finals[layer] = h after last step
        cudaMemcpyAsync(out + (size_t)layer * 262144, pH, 262144 * sizeof(float),
                        cudaMemcpyDeviceToDevice, 0);
    }
}

// round 16
// speedup vs baseline: 1.0068x; 1.0068x over previous
#include <cuda_runtime.h>

// DCRNN encoder (2-layer DCGRU), fp32. B=16,T=32,N=128,D=H=128,K=2 (M=3).
// d_out = [finals (L*B*N*H = 524288 floats) | layer-1 out seq (T*B*N*H = 8388608)]

#define Tn 32
#define Bn 16

typedef unsigned long long ull;

// ---------------- static device scratch (no allocs allowed) ----------------
__device__ float g_Wx[2][384 * 384];    // x-part weights [A;B;C] -> [gates(256)|cand(128)]
__device__ float g_Whg[2][384 * 256];   // h-part gate weights [A;B;C]
__device__ float g_Whc[2][384 * 128];   // h-part cand weights [A;B;C]
__device__ float g_S2[Tn * 128 * 128];      // S_t @ S_t
__device__ float g_XS[Tn * Bn * 128 * 128]; // S   @ x per (t,b)
__device__ float g_X2S[Tn * Bn * 128 * 128];// S^2 @ x
__device__ float g_PRE[Tn * Bn * 128 * 384];// x-contribution (+bias): 0..255 gates, 256..383 cand
__device__ float g_H[Bn * 128 * 128];   // current hidden
__device__ float g_RH[Bn * 128 * 128];  // r * h
__device__ float g_U[Bn * 128 * 128];   // u gate
__device__ float g_OUT0[Tn * Bn * 128 * 128]; // layer-0 output sequence

// ---------------- f32x2 helpers --------------------------------------------
__device__ __forceinline__ ull pk2(float a, float b) {
    ull r;
    asm("mov.b64 %0,{%1,%2};" : "=l"(r) : "r"(__float_as_uint(a)), "r"(__float_as_uint(b)));
    return r;
}
__device__ __forceinline__ ull dup2(float a) { return pk2(a, a); }
__device__ __forceinline__ void upk2(ull v, float& a, float& b) {
    unsigned int x, y;
    asm("mov.b64 {%0,%1},%2;" : "=r"(x), "=r"(y) : "l"(v));
    a = __uint_as_float(x); b = __uint_as_float(y);
}
__device__ __forceinline__ void fma2(ull& c, ull a, ull b) {
    asm("fma.rn.f32x2 %0,%1,%2,%0;" : "+l"(c) : "l"(a), "l"(b));
}

__device__ __forceinline__ void cpy4(float* dst, const float* __restrict__ src, int n4, int tid) {
    float4* d = (float4*)dst;
    const float4* s = (const float4*)src;
    for (int i = tid; i < n4; i += 256) d[i] = s[i];
}

// ---------------- weight prep: fold Chebyshev into [A;B;C] -----------------
__global__ void k_prep_w(const float* __restrict__ Wg0, const float* __restrict__ Wc0,
                         const float* __restrict__ Wg1, const float* __restrict__ Wc1) {
    int idx = blockIdx.x * 256 + threadIdx.x;
    const int PER = 147456 + 98304 + 49152;  // 294912 per layer
    if (idx >= 2 * PER) return;
    int layer = idx / PER, r = idx % PER;
    const float* Wg = layer ? Wg1 : Wg0;
    const float* Wc = layer ? Wc1 : Wc0;
    if (r < 147456) {                       // g_Wx [384][384] : x features (dcat = k)
        int k2 = r / 384, o = r % 384, part = k2 >> 7, k = k2 & 127;
        const float* W; int oc, oo;
        if (o < 256) { W = Wg; oc = 256; oo = o; } else { W = Wc; oc = 128; oo = o - 256; }
        int base = k * 3;
        float v = (part == 0) ? W[(base + 0) * oc + oo] - W[(base + 2) * oc + oo]
                : (part == 1) ? W[(base + 1) * oc + oo]
                              : 2.f * W[(base + 2) * oc + oo];
        g_Wx[layer][k2 * 384 + o] = v;
    } else if (r < 245760) {                // g_Whg [384][256] : h features (dcat = 128+k)
        int rr = r - 147456, k2 = rr / 256, o = rr % 256, part = k2 >> 7, k = k2 & 127;
        int base = (128 + k) * 3;
        float v = (part == 0) ? Wg[(base + 0) * 256 + o] - Wg[(base + 2) * 256 + o]
                : (part == 1) ? Wg[(base + 1) * 256 + o]
                              : 2.f * Wg[(base + 2) * 256 + o];
        g_Whg[layer][k2 * 256 + o] = v;
    } else {                                // g_Whc [384][128]
        int rr = r - 245760, k2 = rr / 128, o = rr % 128, part = k2 >> 7, k = k2 & 127;
        int base = (128 + k) * 3;
        float v = (part == 0) ? Wc[(base + 0) * 128 + o] - Wc[(base + 2) * 128 + o]
                : (part == 1) ? Wc[(base + 1) * 128 + o]
                              : 2.f * Wc[(base + 2) * 128 + o];
        g_Whc[layer][k2 * 128 + o] = v;
    }
}

// ---------------- S2[t] = S_t @ S_t  (grid: 32 x 4, tile 32x128) -----------
__global__ void __launch_bounds__(256)
k_s2(const float* __restrict__ sup) {
    extern __shared__ float sm[];
    float* sX = sm;            // 128x128
    float* sA = sm + 16384;    // 32x128
    int tid = threadIdx.x, tx = tid & 31, ty = tid >> 5;
    int t = blockIdx.x, r0 = blockIdx.y * 32;
    const float* S = sup + t * 16384;
    cpy4(sX, S, 4096, tid);
    cpy4(sA, S + r0 * 128, 1024, tid);
    __syncthreads();
    ull acc[4][2] = {};
#pragma unroll 4
    for (int k = 0; k < 128; k++) {
        ulonglong2 bv = *(const ulonglong2*)(sX + k * 128 + tx * 4);
#pragma unroll
        for (int i = 0; i < 4; i++) {
            ull av = dup2(sA[(ty * 4 + i) * 128 + k]);
            fma2(acc[i][0], av, bv.x);
            fma2(acc[i][1], av, bv.y);
        }
    }
#pragma unroll
    for (int i = 0; i < 4; i++) {
        float4 v;
        upk2(acc[i][0], v.x, v.y);
        upk2(acc[i][1], v.z, v.w);
        *(float4*)(g_S2 + t * 16384 + (r0 + ty * 4 + i) * 128 + tx * 4) = v;
    }
}

// ------- XS = S@x, X2S = S^2@x for all (t,b) (grid: 512 x 4) ---------------
__global__ void __launch_bounds__(256)
k_pre_graph(const float* __restrict__ Xin, int mode, const float* __restrict__ sup) {
    extern __shared__ float sm[];
    float* sX  = sm;           // 16384
    float* sA  = sm + 16384;   // 4096
    float* sA2 = sm + 20480;   // 4096
    int tid = threadIdx.x, tx = tid & 31, ty = tid >> 5;
    int tb = blockIdx.x, t = tb >> 4, b = tb & 15, r0 = blockIdx.y * 32;
    const float* X = (mode == 0) ? Xin + (size_t)(b * Tn + t) * 16384
                                 : g_OUT0 + (size_t)tb * 16384;
    cpy4(sX, X, 4096, tid);
    cpy4(sA,  sup  + t * 16384 + r0 * 128, 1024, tid);
    cpy4(sA2, g_S2 + t * 16384 + r0 * 128, 1024, tid);
    __syncthreads();
    ull a1[4][2] = {}, a2[4][2] = {};
#pragma unroll 2
    for (int k = 0; k < 128; k++) {
        ulonglong2 bv = *(const ulonglong2*)(sX + k * 128 + tx * 4);
#pragma unroll
        for (int i = 0; i < 4; i++) {
            ull av = dup2(sA[(ty * 4 + i) * 128 + k]);
            fma2(a1[i][0], av, bv.x);
            fma2(a1[i][1], av, bv.y);
            ull aw = dup2(sA2[(ty * 4 + i) * 128 + k]);
            fma2(a2[i][0], aw, bv.x);
            fma2(a2[i][1], aw, bv.y);
        }
    }
#pragma unroll
    for (int i = 0; i < 4; i++) {
        float4 v;
        upk2(a1[i][0], v.x, v.y); upk2(a1[i][1], v.z, v.w);
        *(float4*)(g_XS + (size_t)tb * 16384 + (r0 + ty * 4 + i) * 128 + tx * 4) = v;
        upk2(a2[i][0], v.x, v.y); upk2(a2[i][1], v.z, v.w);
        *(float4*)(g_X2S + (size_t)tb * 16384 + (r0 + ty * 4 + i) * 128 + tx * 4) = v;
    }
}

// ------- PRE = [x|Sx|S2x]@Wx + bias (grid: 512 x 4 x 3) --------------------
__global__ void __launch_bounds__(256)
k_pre_dense(const float* __restrict__ Xin, int mode, int layer,
            const float* __restrict__ bg, const float* __restrict__ bc) {
    extern __shared__ float sm[];
    float* sA = sm;            // 4096 (32x128)
    float* sW = sm + 4096;     // 16384 (128x128)
    int tid = threadIdx.x, tx = tid & 31, ty = tid >> 5;
    int tb = blockIdx.x, t = tb >> 4, b = tb & 15;
    int r0 = blockIdx.y * 32, c0 = blockIdx.z * 128;
    const float* W = g_Wx[layer];
    ull acc[4][2] = {};
    for (int ch = 0; ch < 3; ch++) {
        const float* As;
        if (ch == 0)
            As = (mode == 0) ? Xin + (size_t)(b * Tn + t) * 16384
                             : g_OUT0 + (size_t)tb * 16384;
        else if (ch == 1) As = g_XS + (size_t)tb * 16384;
        else              As = g_X2S + (size_t)tb * 16384;
        __syncthreads();
        cpy4(sA, As + r0 * 128, 1024, tid);
        for (int i = tid; i < 4096; i += 256) {
            int kk = i >> 5, cc = (i & 31) * 4;
            *(float4*)(sW + kk * 128 + cc) =
                *(const float4*)(W + (size_t)(ch * 128 + kk) * 384 + c0 + cc);
        }
        __syncthreads();
#pragma unroll 4
        for (int k = 0; k < 128; k++) {
            ulonglong2 bv = *(const ulonglong2*)(sW + k * 128 + tx * 4);
#pragma unroll
            for (int i = 0; i < 4; i++) {
                ull av = dup2(sA[(ty * 4 + i) * 128 + k]);
                fma2(acc[i][0], av, bv.x);
                fma2(acc[i][1], av, bv.y);
            }
        }
    }
    int oc = c0 + tx * 4;
    float4 bias;
    if (oc < 256) bias = *(const float4*)(bg + oc);
    else          bias = *(const float4*)(bc + oc - 256);
#pragma unroll
    for (int i = 0; i < 4; i++) {
        float4 v;
        upk2(acc[i][0], v.x, v.y); upk2(acc[i][1], v.z, v.w);
        v.x += bias.x; v.y += bias.y; v.z += bias.z; v.w += bias.w;
        *(float4*)(g_PRE + ((size_t)tb * 128 + r0 + ty * 4 + i) * 384 + oc) = v;
    }
}

// ------- per-step kernel 1: graph-conv(h) + gate GEMM + sigmoid + r*h ------
// grid (16 batches, 4 row-tiles, 2 col-tiles[r|u]), 192KB smem
__global__ void __launch_bounds__(256)
k_gates(int t, int layer, const float* __restrict__ sup) {
    extern __shared__ float sm[];
    float* sHb  = sm;           // 16384 : full h_b
    float* sS   = sm + 16384;   // 4096
    float* sS2  = sm + 20480;   // 4096
    float* sSh  = sm + 24576;   // 4096
    float* sS2h = sm + 28672;   // 4096
    float* sW   = sm + 32768;   // 16384
    int tid = threadIdx.x, tx = tid & 31, ty = tid >> 5;
    int b = blockIdx.x, r0 = blockIdx.y * 32, ct = blockIdx.z, c0 = ct * 128;
    cpy4(sHb, g_H + b * 16384, 4096, tid);
    cpy4(sS,  sup  + t * 16384 + r0 * 128, 1024, tid);
    cpy4(sS2, g_S2 + t * 16384 + r0 * 128, 1024, tid);
    __syncthreads();
    // phase 1: Sh, S2h row tiles
    {
        ull a1[4][2] = {}, a2[4][2] = {};
#pragma unroll 2
        for (int k = 0; k < 128; k++) {
            ulonglong2 bv = *(const ulonglong2*)(sHb + k * 128 + tx * 4);
#pragma unroll
            for (int i = 0; i < 4; i++) {
                ull av = dup2(sS[(ty * 4 + i) * 128 + k]);
                fma2(a1[i][0], av, bv.x); fma2(a1[i][1], av, bv.y);
                ull aw = dup2(sS2[(ty * 4 + i) * 128 + k]);
                fma2(a2[i][0], aw, bv.x); fma2(a2[i][1], aw, bv.y);
            }
        }
#pragma unroll
        for (int i = 0; i < 4; i++) {
            float4 v;
            upk2(a1[i][0], v.x, v.y); upk2(a1[i][1], v.z, v.w);
            *(float4*)(sSh + (ty * 4 + i) * 128 + tx * 4) = v;
            upk2(a2[i][0], v.x, v.y); upk2(a2[i][1], v.z, v.w);
            *(float4*)(sS2h + (ty * 4 + i) * 128 + tx * 4) = v;
        }
    }
    // phase 2: [h|Sh|S2h] @ Whg[:, c0:c0+128]
    const float* W = g_Whg[layer];
    ull acc[4][2] = {};
    for (int ch = 0; ch < 3; ch++) {
        __syncthreads();
        for (int i = tid; i < 4096; i += 256) {
            int kk = i >> 5, cc = (i & 31) * 4;
            *(float4*)(sW + kk * 128 + cc) =
                *(const float4*)(W + (size_t)(ch * 128 + kk) * 256 + c0 + cc);
        }
        __syncthreads();
        const float* A = (ch == 0) ? sHb + r0 * 128 : (ch == 1) ? sSh : sS2h;
#pragma unroll 4
        for (int k = 0; k < 128; k++) {
            ulonglong2 bv = *(const ulonglong2*)(sW + k * 128 + tx * 4);
#pragma unroll
            for (int i = 0; i < 4; i++) {
                ull av = dup2(A[(ty * 4 + i) * 128 + k]);
                fma2(acc[i][0], av, bv.x);
                fma2(acc[i][1], av, bv.y);
            }
        }
    }
    int tb = t * Bn + b;
#pragma unroll
    for (int i = 0; i < 4; i++) {
        int row = r0 + ty * 4 + i;
        float4 v;
        upk2(acc[i][0], v.x, v.y); upk2(acc[i][1], v.z, v.w);
        float4 p = *(const float4*)(g_PRE + ((size_t)tb * 128 + row) * 384 + c0 + tx * 4);
        v.x = 1.f / (1.f + expf(-(v.x + p.x)));
        v.y = 1.f / (1.f + expf(-(v.y + p.y)));
        v.z = 1.f / (1.f + expf(-(v.z + p.z)));
        v.w = 1.f / (1.f + expf(-(v.w + p.w)));
        int off = b * 16384 + row * 128 + tx * 4;
        if (ct == 0) {  // r gate -> rh
            float4 h = *(const float4*)(sHb + row * 128 + tx * 4);
            v.x *= h.x; v.y *= h.y; v.z *= h.z; v.w *= h.w;
            *(float4*)(g_RH + off) = v;
        } else {        // u gate
            *(float4*)(g_U + off) = v;
        }
    }
}

// ------- per-step kernel 2: graph-conv(rh) + cand GEMM + tanh + GRU update -
// grid (16 batches, 4 row-tiles), 192KB smem
__global__ void __launch_bounds__(256)
k_cand(int t, int layer, const float* __restrict__ sup, float* __restrict__ dout1) {
    extern __shared__ float sm[];
    float* sRb  = sm;           // 16384 : full rh_b
    float* sS   = sm + 16384;
    float* sS2  = sm + 20480;
    float* sSh  = sm + 24576;
    float* sS2h = sm + 28672;
    float* sW   = sm + 32768;
    int tid = threadIdx.x, tx = tid & 31, ty = tid >> 5;
    int b = blockIdx.x, r0 = blockIdx.y * 32;
    cpy4(sRb, g_RH + b * 16384, 4096, tid);
    cpy4(sS,  sup  + t * 16384 + r0 * 128, 1024, tid);
    cpy4(sS2, g_S2 + t * 16384 + r0 * 128, 1024, tid);
    __syncthreads();
    {
        ull a1[4][2] = {}, a2[4][2] = {};
#pragma unroll 2
        for (int k = 0; k < 128; k++) {
            ulonglong2 bv = *(const ulonglong2*)(sRb + k * 128 + tx * 4);
#pragma unroll
            for (int i = 0; i < 4; i++) {
                ull av = dup2(sS[(ty * 4 + i) * 128 + k]);
                fma2(a1[i][0], av, bv.x); fma2(a1[i][1], av, bv.y);
                ull aw = dup2(sS2[(ty * 4 + i) * 128 + k]);
                fma2(a2[i][0], aw, bv.x); fma2(a2[i][1], aw, bv.y);
            }
        }
#pragma unroll
        for (int i = 0; i < 4; i++) {
            float4 v;
            upk2(a1[i][0], v.x, v.y); upk2(a1[i][1], v.z, v.w);
            *(float4*)(sSh + (ty * 4 + i) * 128 + tx * 4) = v;
            upk2(a2[i][0], v.x, v.y); upk2(a2[i][1], v.z, v.w);
            *(float4*)(sS2h + (ty * 4 + i) * 128 + tx * 4) = v;
        }
    }
    const float* W = g_Whc[layer];
    ull acc[4][2] = {};
    for (int ch = 0; ch < 3; ch++) {
        __syncthreads();
        for (int i = tid; i < 4096; i += 256) {
            int kk = i >> 5, cc = (i & 31) * 4;
            *(float4*)(sW + kk * 128 + cc) =
                *(const float4*)(W + (size_t)(ch * 128 + kk) * 128 + cc);
        }
        __syncthreads();
        const float* A = (ch == 0) ? sRb + r0 * 128 : (ch == 1) ? sSh : sS2h;
#pragma unroll 4
        for (int k = 0; k < 128; k++) {
            ulonglong2 bv = *(const ulonglong2*)(sW + k * 128 + tx * 4);
#pragma unroll
            for (int i = 0; i < 4; i++) {
                ull av = dup2(A[(ty * 4 + i) * 128 + k]);
                fma2(acc[i][0], av, bv.x);
                fma2(acc[i][1], av, bv.y);
            }
        }
    }
    int tb = t * Bn + b;
    float* outp = layer ? dout1 : g_OUT0;
#pragma unroll
    for (int i = 0; i < 4; i++) {
        int row = r0 + ty * 4 + i;
        float4 v;
        upk2(acc[i][0], v.x, v.y); upk2(acc[i][1], v.z, v.w);
        float4 p = *(const float4*)(g_PRE + ((size_t)tb * 128 + row) * 384 + 256 + tx * 4);
        v.x = tanhf(v.x + p.x);
        v.y = tanhf(v.y + p.y);
        v.z = tanhf(v.z + p.z);
        v.w = tanhf(v.w + p.w);
        int off = b * 16384 + row * 128 + tx * 4;
        float4 u = *(const float4*)(g_U + off);
        float4 h = *(const float4*)(g_H + off);
        float4 hn;
        hn.x = u.x * h.x + (1.f - u.x) * v.x;
        hn.y = u.y * h.y + (1.f - u.y) * v.y;
        hn.z = u.z * h.z + (1.f - u.z) * v.z;
        hn.w = u.w * h.w + (1.f - u.w) * v.w;
        *(float4*)(g_H + off) = hn;
        *(float4*)(outp + (size_t)tb * 16384 + row * 128 + tx * 4) = hn;
    }
}

// ---------------------------------------------------------------------------
extern "C" void kernel_launch(void* const* d_in, const int* in_sizes, int n_in,
                              void* d_out, int out_size) {
    const float* inputs = (const float*)d_in[0];
    const float* ihs    = (const float*)d_in[1];
    const float* sup    = (const float*)d_in[2];
    const float* Wg0 = (const float*)d_in[3];
    const float* bg0 = (const float*)d_in[4];
    const float* Wc0 = (const float*)d_in[5];
    const float* bc0 = (const float*)d_in[6];
    const float* Wg1 = (const float*)d_in[7];
    const float* bg1 = (const float*)d_in[8];
    const float* Wc1 = (const float*)d_in[9];
    const float* bc1 = (const float*)d_in[10];
    float* out = (float*)d_out;

    cudaFuncSetAttribute(k_s2,        cudaFuncAttributeMaxDynamicSharedMemorySize, 81920);
    cudaFuncSetAttribute(k_pre_graph, cudaFuncAttributeMaxDynamicSharedMemorySize, 98304);
    cudaFuncSetAttribute(k_pre_dense, cudaFuncAttributeMaxDynamicSharedMemorySize, 81920);
    cudaFuncSetAttribute(k_gates,     cudaFuncAttributeMaxDynamicSharedMemorySize, 196608);
    cudaFuncSetAttribute(k_cand,      cudaFuncAttributeMaxDynamicSharedMemorySize, 196608);

    float* pH = nullptr;
    cudaGetSymbolAddress((void**)&pH, g_H);

    k_prep_w<<<2304, 256>>>(Wg0, Wc0, Wg1, Wc1);
    k_s2<<<dim3(32, 4), 256, 81920>>>(sup);

    for (int layer = 0; layer < 2; layer++) {
        cudaMemcpyAsync(pH, ihs + (size_t)layer * 262144, 262144 * sizeof(float),
                        cudaMemcpyDeviceToDevice, 0);
        k_pre_graph<<<dim3(512, 4), 256, 98304>>>(inputs, layer, sup);
        k_pre_dense<<<dim3(512, 4, 3), 256, 81920>>>(
            inputs, layer, layer, layer ? bg1 : bg0, layer ? bc1 : bc0);
        for (int t = 0; t < Tn; t++) {
            k_gates<<<dim3(16, 4, 2), 256, 196608>>>(t, layer, sup);
            k_cand<<<dim3(16, 4), 256, 196608>>>(t, layer, sup, out + 524288);
        }
        // finals[layer] = h after last step
        cudaMemcpyAsync(out + (size_t)layer * 262144, pH, 262144 * sizeof(float),
                        cudaMemcpyDeviceToDevice, 0);
    }
}